// round 6
// baseline (speedup 1.0000x reference)
#include <cuda_runtime.h>
#include <math.h>

// MT 1D forward + loss, fused. Output: [total, loss_rhoa, loss_phase].
//
// Layer map as 2x2 complex matrix on (U,V) (U=N+D, V=N-D basis, x=Z/Zj):
//   M_j = [[1, -r*E],[r, -E]],  r = (g-1)/(g+1), g = sqrt(rho_j/rho_{j-1}),
//   E = exp(-a)(cos a - i sin a), a = s*coef_j, coef_j = t_j*sqrt(2*mu/rho_j)
// 8-way chain split: lane q of each 8-lane group accumulates P_q = prod of
// its 32-layer segment (matrix-matrix, 16 FMA/step); a 3-level shfl_xor tree
// composes Q = P7...P0; apply to v0 = (x0+1, x0-1). Scale-invariant
// throughout (renorm by column-0 norm every 8 steps).
// app_res = rho_0*|N|^2/|D|^2; phase = atan2(A+B, A-B) (division-free).

#define MUF 1.25663706143591729e-6f   // 4*pi*1e-7
#define TWO_PI_F 6.2831853071795864f
#define RAD2DEG_F 57.295779513082321f
#define SPLIT 8

__device__ float2 g_part[1024];
__device__ unsigned int g_ticket;     // zero-init; last block resets each launch

__device__ __forceinline__ float frcp_fast(float x) {
    float r;
    asm("rcp.approx.ftz.f32 %0, %1;" : "=f"(r) : "f"(x));
    return r;
}

struct CMat {   // 2x2 complex matrix
    float m00r, m00i, m01r, m01i, m10r, m10i, m11r, m11i;
};

// C = A * B (complex 2x2 matmul, 32 FMA)
__device__ __forceinline__ CMat cmatmul(const CMat& A, const CMat& B)
{
    CMat C;
    C.m00r = A.m00r*B.m00r - A.m00i*B.m00i + A.m01r*B.m10r - A.m01i*B.m10i;
    C.m00i = A.m00r*B.m00i + A.m00i*B.m00r + A.m01r*B.m10i + A.m01i*B.m10r;
    C.m01r = A.m00r*B.m01r - A.m00i*B.m01i + A.m01r*B.m11r - A.m01i*B.m11i;
    C.m01i = A.m00r*B.m01i + A.m00i*B.m01r + A.m01r*B.m11i + A.m01i*B.m11r;
    C.m10r = A.m10r*B.m00r - A.m10i*B.m00i + A.m11r*B.m10r - A.m11i*B.m10i;
    C.m10i = A.m10r*B.m00i + A.m10i*B.m00r + A.m11r*B.m10i + A.m11i*B.m10r;
    C.m11r = A.m10r*B.m01r - A.m10i*B.m01i + A.m11r*B.m11r - A.m11i*B.m11i;
    C.m11i = A.m10r*B.m01i + A.m10i*B.m01r + A.m11r*B.m11i + A.m11i*B.m11r;
    return C;
}

__device__ __forceinline__ CMat shfl_xor_mat(const CMat& M, int mask)
{
    const unsigned FULL = 0xffffffffu;
    CMat R;
    R.m00r = __shfl_xor_sync(FULL, M.m00r, mask);
    R.m00i = __shfl_xor_sync(FULL, M.m00i, mask);
    R.m01r = __shfl_xor_sync(FULL, M.m01r, mask);
    R.m01i = __shfl_xor_sync(FULL, M.m01i, mask);
    R.m10r = __shfl_xor_sync(FULL, M.m10r, mask);
    R.m10i = __shfl_xor_sync(FULL, M.m10i, mask);
    R.m11r = __shfl_xor_sync(FULL, M.m11r, mask);
    R.m11i = __shfl_xor_sync(FULL, M.m11i, mask);
    return R;
}

// P = M_i * P with M_i = [[1, -rE],[r, -E]]  (16 FMA + E-math)
__device__ __forceinline__ void mat_step(float2 L, float s, CMat& P)
{
    float a  = s * L.x;
    float em = __expf(-a);
    float sa, ca;
    __sincosf(a, &sa, &ca);
    float er = em * ca;                  // E = er - i*ei
    float ei = em * sa;
    float r  = L.y;

    // X = E*p10, Y = E*p11
    float Xr = er * P.m10r + ei * P.m10i;
    float Xi = er * P.m10i - ei * P.m10r;
    float Yr = er * P.m11r + ei * P.m11i;
    float Yi = er * P.m11i - ei * P.m11r;

    float n00r = fmaf(-r, Xr, P.m00r);
    float n00i = fmaf(-r, Xi, P.m00i);
    float n01r = fmaf(-r, Yr, P.m01r);
    float n01i = fmaf(-r, Yi, P.m01i);
    float n10r = fmaf( r, P.m00r, -Xr);
    float n10i = fmaf( r, P.m00i, -Xi);
    float n11r = fmaf( r, P.m01r, -Yr);
    float n11i = fmaf( r, P.m01i, -Yi);
    P.m00r = n00r; P.m00i = n00i; P.m01r = n01r; P.m01i = n01i;
    P.m10r = n10r; P.m10i = n10i; P.m11r = n11r; P.m11i = n11i;
}

__global__ __launch_bounds__(128)
void mt_fused(const float* __restrict__ res,
              const float* __restrict__ thick,
              const float* __restrict__ freq,
              const float* __restrict__ orhoa,
              const float* __restrict__ ophase,
              float* __restrict__ out,
              int nz, int nf, float inv_nf)
{
    __shared__ float2 lay[512];        // (coef_j, r_j), deepest layer first
    __shared__ float  sc_x0, sc_lrho0;
    __shared__ float2 red[4];
    __shared__ int    is_last;

    const int nl  = nz - 1;
    const int tid = threadIdx.x;

    for (int i = tid; i < nl; i += blockDim.x) {
        int   j   = nl - 1 - i;
        float rho = res[j];
        float t   = thick[j];
        float g   = (j >= 1) ? sqrtf(rho / res[j - 1]) : 1.0f;
        lay[i] = make_float2(t * sqrtf(2.0f * MUF / rho),
                             (g - 1.0f) / (g + 1.0f));
    }
    if (tid == 0) {
        sc_x0    = sqrtf(res[nz - 1] / res[nz - 2]);
        sc_lrho0 = log10f(res[0]);
    }
    __syncthreads();

    const int gtid = blockIdx.x * blockDim.x + tid;
    const int fq   = gtid >> 3;         // frequency index
    const int q    = gtid & 7;          // segment lane (0..7)
    float lr = 0.0f, lp = 0.0f;

    if (fq < nf) {
        float omega = TWO_PI_F * freq[fq];
        float s     = sqrtf(omega);

        const int len   = (nl + SPLIT - 1) / SPLIT;   // 32 for nl=255
        const int start = q * len;
        const int end   = min(start + len, nl);

        CMat P = {1.0f, 0.0f, 0.0f, 0.0f, 0.0f, 0.0f, 1.0f, 0.0f};

        int i = start;
        for (; i + 8 <= end; i += 8) {
            #pragma unroll
            for (int u = 0; u < 8; ++u)
                mat_step(lay[i + u], s, P);
            // renorm by column-0 norm (col0 = image of passive vector (1,0))
            float m = frcp_fast(fabsf(P.m00r) + fabsf(P.m00i)
                              + fabsf(P.m10r) + fabsf(P.m10i));
            P.m00r *= m; P.m00i *= m; P.m01r *= m; P.m01i *= m;
            P.m10r *= m; P.m10i *= m; P.m11r *= m; P.m11i *= m;
        }
        for (; i < end; ++i)
            mat_step(lay[i], s, P);

        // Compose Q = P7*P6*...*P0 across the 8-lane group (3 levels).
        // At mask b: lane with (q&b)==0 holds the "lower" product.
        #pragma unroll
        for (int b = 1; b <= 4; b <<= 1) {
            CMat R = shfl_xor_mat(P, b);
            P = ((q & b) == 0) ? cmatmul(R, P) : cmatmul(P, R);
            float m = frcp_fast(fabsf(P.m00r) + fabsf(P.m00i)
                              + fabsf(P.m10r) + fabsf(P.m10i));
            P.m00r *= m; P.m00i *= m; P.m01r *= m; P.m01i *= m;
            P.m10r *= m; P.m10i *= m; P.m11r *= m; P.m11i *= m;
        }

        if (q == 0) {
            // apply to v0 = (x0+1, x0-1), x0 real
            float u0 = sc_x0 + 1.0f, v0 = sc_x0 - 1.0f;
            float Ur = P.m00r * u0 + P.m01r * v0;
            float Ui = P.m00i * u0 + P.m01i * v0;
            float Vr = P.m10r * u0 + P.m11r * v0;
            float Vi = P.m10i * u0 + P.m11i * v0;

            float Nr = Ur + Vr, Ni = Ui + Vi;
            float Dr = Ur - Vr, Di = Ui - Vi;

            float n2 = fmaxf(Nr * Nr + Ni * Ni, 1e-30f);
            float d2 = fmaxf(Dr * Dr + Di * Di, 1e-30f);
            float A  = Nr * Dr + Ni * Di;
            float B  = Ni * Dr - Nr * Di;

            float e1 = sc_lrho0 + log10f(n2) - log10f(d2) - log10f(orhoa[fq]);
            float ph = atan2f(A + B, A - B) * RAD2DEG_F;
            float e2 = ph - ophase[fq];
            lr = e1 * e1;
            lp = e2 * e2;
        }
    }

    // deterministic block reduction (128 threads = 4 warps)
    const unsigned FULL = 0xffffffffu;
    #pragma unroll
    for (int o = 16; o > 0; o >>= 1) {
        lr += __shfl_down_sync(FULL, lr, o);
        lp += __shfl_down_sync(FULL, lp, o);
    }
    int wid = tid >> 5, lane = tid & 31;
    if (lane == 0) red[wid] = make_float2(lr, lp);
    __syncthreads();
    if (tid == 0) {
        float slr = red[0].x + red[1].x + red[2].x + red[3].x;
        float slp = red[0].y + red[1].y + red[2].y + red[3].y;
        g_part[blockIdx.x] = make_float2(slr, slp);
        __threadfence();
        unsigned t = atomicAdd(&g_ticket, 1u);
        is_last = (t == gridDim.x - 1) ? 1 : 0;
    }
    __syncthreads();

    if (is_last) {
        __threadfence();
        float flr = 0.0f, flp = 0.0f;
        if (tid < 32) {
            for (int i = tid; i < (int)gridDim.x; i += 32) {
                volatile float* vp = (volatile float*)&g_part[i];
                flr += vp[0];
                flp += vp[1];
            }
            #pragma unroll
            for (int o = 16; o > 0; o >>= 1) {
                flr += __shfl_down_sync(FULL, flr, o);
                flp += __shfl_down_sync(FULL, flp, o);
            }
            if (tid == 0) {
                float mlr = flr * inv_nf;
                float mlp = flp * inv_nf;
                out[0] = mlr + 10.0f * mlp;   // LAMBDA_RHOA=1, LAMBDA_PHASE=10
                out[1] = mlr;
                out[2] = mlp;
                g_ticket = 0;                 // reset for next graph replay
            }
        }
    }
}

extern "C" void kernel_launch(void* const* d_in, const int* in_sizes, int n_in,
                              void* d_out, int out_size)
{
    const float* res = (const float*)d_in[0];
    const float* th  = (const float*)d_in[1];
    const float* fr  = (const float*)d_in[2];
    const float* orh = (const float*)d_in[3];
    const float* oph = (const float*)d_in[4];
    int nz = in_sizes[0];
    int nf = in_sizes[2];

    const int threads = 128;
    long long total = (long long)nf * SPLIT;
    int blocks = (int)((total + threads - 1) / threads);   // 1024 for NF=16384
    if (blocks > 1024) blocks = 1024;

    mt_fused<<<blocks, threads>>>(res, th, fr, orh, oph,
                                  (float*)d_out, nz, nf, 1.0f / (float)nf);
}

// round 7
// speedup vs baseline: 1.4330x; 1.4330x over previous
#include <cuda_runtime.h>
#include <math.h>

// MT 1D forward + loss, fused. Output: [total, loss_rhoa, loss_phase].
//
// Layer map on (U,V) (U=N+D, V=N-D, x=Z/Zj normalized):
//   M_j = [[1, -r*E],[r, -E]],  r=(g-1)/(g+1), g=sqrt(rho_j/rho_{j-1})
//   E = exp(-a)(cos a - i sin a), a = s*coef_j, coef_j = t_j*sqrt(2*mu/rho_j)
// 2-way chain split at WARP granularity (no intra-warp divergence):
//   warps 0-3 ("vector"): deepest ceil(nl/2) layers applied to v0 (12 FMA/step)
//   warps 4-7 ("matrix"): remaining layers as 2x2 product   (16 FMA/step)
// Combine: vector warp writes v to shared; matrix warp applies P*v, computes
// loss. Scale-invariant throughout (renorm every 8 steps); final outputs are
// division-free: app_res = rho_0*|N|^2/|D|^2 via logs, phase = atan2(A+B,A-B).

#define MUF 1.25663706143591729e-6f   // 4*pi*1e-7
#define TWO_PI_F 6.2831853071795864f
#define RAD2DEG_F 57.295779513082321f

__device__ float2 g_part[256];
__device__ unsigned int g_ticket;     // zero-init; last block resets each launch

__device__ __forceinline__ float frcp_fast(float x) {
    float r;
    asm("rcp.approx.ftz.f32 %0, %1;" : "=f"(r) : "f"(x));
    return r;
}

__device__ __forceinline__ void e_math(float2 L, float s,
                                       float& er, float& ei)
{
    float a  = s * L.x;
    float em = __expf(-a);
    float sa, ca;
    __sincosf(a, &sa, &ca);
    er = em * ca;                      // E = er - i*ei
    ei = em * sa;
}

__global__ __launch_bounds__(256, 1)
void mt_fused(const float* __restrict__ res,
              const float* __restrict__ thick,
              const float* __restrict__ freq,
              const float* __restrict__ orhoa,
              const float* __restrict__ ophase,
              float* __restrict__ out,
              int nz, int nf, float inv_nf)
{
    __shared__ float2 lay[512];        // (coef_j, r_j), deepest layer first
    __shared__ float4 exch[128];       // vector-warp results (4 pairs x 32)
    __shared__ float  sc_x0, sc_lrho0;
    __shared__ float2 red[8];
    __shared__ int    is_last;

    const int nl  = nz - 1;
    const int tid = threadIdx.x;

    for (int i = tid; i < nl; i += blockDim.x) {
        int   j   = nl - 1 - i;                    // deepest first
        float rho = res[j];
        float t   = thick[j];
        float g   = (j >= 1) ? sqrtf(rho / res[j - 1]) : 1.0f;
        lay[i] = make_float2(t * sqrtf(2.0f * MUF / rho),
                             (g - 1.0f) / (g + 1.0f));
    }
    if (tid == 0) {
        sc_x0    = sqrtf(res[nz - 1] / res[nz - 2]);
        sc_lrho0 = log10f(res[0]);
    }
    __syncthreads();

    const int wid  = tid >> 5;
    const int lane = tid & 31;
    const int pair = wid & 3;          // 0..3
    const int role = wid >> 2;         // 0 = vector (deep half), 1 = matrix
    const int fq   = blockIdx.x * 128 + pair * 32 + lane;
    const int vlen = (nl + 1) >> 1;    // 128 for nl=255

    float lr = 0.0f, lp = 0.0f;

    float omega = TWO_PI_F * freq[min(fq, nf - 1)];
    float s     = sqrtf(omega);

    if (role == 0) {
        // ---- vector warp: deepest vlen layers applied to v0 ----
        float x0 = sc_x0;
        float Ur = x0 + 1.0f, Ui = 0.0f;
        float Vr = x0 - 1.0f, Vi = 0.0f;

        int i = 0;
        for (; i + 8 <= vlen; i += 8) {
            #pragma unroll
            for (int u = 0; u < 8; ++u) {
                float er, ei;
                e_math(lay[i + u], s, er, ei);
                float wr = er * Vr + ei * Vi;      // w = E*V
                float wi = er * Vi - ei * Vr;
                float r  = lay[i + u].y;
                float nUr = fmaf(-r, wr, Ur);
                float nUi = fmaf(-r, wi, Ui);
                float nVr = fmaf( r, Ur, -wr);
                float nVi = fmaf( r, Ui, -wi);
                Ur = nUr; Ui = nUi; Vr = nVr; Vi = nVi;
            }
            float m = frcp_fast(fabsf(Ur) + fabsf(Ui));
            Ur *= m; Ui *= m; Vr *= m; Vi *= m;
        }
        for (; i < vlen; ++i) {
            float er, ei;
            e_math(lay[i], s, er, ei);
            float wr = er * Vr + ei * Vi;
            float wi = er * Vi - ei * Vr;
            float r  = lay[i].y;
            float nUr = fmaf(-r, wr, Ur);
            float nUi = fmaf(-r, wi, Ui);
            float nVr = fmaf( r, Ur, -wr);
            float nVi = fmaf( r, Ui, -wi);
            Ur = nUr; Ui = nUi; Vr = nVr; Vi = nVi;
        }
        exch[pair * 32 + lane] = make_float4(Ur, Ui, Vr, Vi);
    } else {
        // ---- matrix warp: remaining layers as a 2x2 complex product ----
        // P = M_{nl-1} ... M_{vlen};  P_new = M*P:
        //   row0' = row0 - r*(E*row1_of_P? ) -- careful: M=[[1,-rE],[r,-E]]
        //   new_row0 = row0 - rE*row1 ; new_row1 = r*row0 - E*row1
        float p00r = 1.0f, p00i = 0.0f, p01r = 0.0f, p01i = 0.0f;
        float p10r = 0.0f, p10i = 0.0f, p11r = 1.0f, p11i = 0.0f;

        int i = vlen;
        for (; i + 8 <= nl; i += 8) {
            #pragma unroll
            for (int u = 0; u < 8; ++u) {
                float er, ei;
                e_math(lay[i + u], s, er, ei);
                float r = lay[i + u].y;
                // X = E*p10, Y = E*p11   (E = er - i*ei)
                float Xr = er * p10r + ei * p10i;
                float Xi = er * p10i - ei * p10r;
                float Yr = er * p11r + ei * p11i;
                float Yi = er * p11i - ei * p11r;
                float n00r = fmaf(-r, Xr, p00r);
                float n00i = fmaf(-r, Xi, p00i);
                float n01r = fmaf(-r, Yr, p01r);
                float n01i = fmaf(-r, Yi, p01i);
                float n10r = fmaf( r, p00r, -Xr);
                float n10i = fmaf( r, p00i, -Xi);
                float n11r = fmaf( r, p01r, -Yr);
                float n11i = fmaf( r, p01i, -Yi);
                p00r = n00r; p00i = n00i; p01r = n01r; p01i = n01i;
                p10r = n10r; p10i = n10i; p11r = n11r; p11i = n11i;
            }
            float m = frcp_fast(fabsf(p00r) + fabsf(p00i)
                              + fabsf(p10r) + fabsf(p10i));
            p00r *= m; p00i *= m; p01r *= m; p01i *= m;
            p10r *= m; p10i *= m; p11r *= m; p11i *= m;
        }
        for (; i < nl; ++i) {
            float er, ei;
            e_math(lay[i], s, er, ei);
            float r = lay[i].y;
            float Xr = er * p10r + ei * p10i;
            float Xi = er * p10i - ei * p10r;
            float Yr = er * p11r + ei * p11i;
            float Yi = er * p11i - ei * p11r;
            float n00r = fmaf(-r, Xr, p00r);
            float n00i = fmaf(-r, Xi, p00i);
            float n01r = fmaf(-r, Yr, p01r);
            float n01i = fmaf(-r, Yi, p01i);
            float n10r = fmaf( r, p00r, -Xr);
            float n10i = fmaf( r, p00i, -Xi);
            float n11r = fmaf( r, p01r, -Yr);
            float n11i = fmaf( r, p01i, -Yi);
            p00r = n00r; p00i = n00i; p01r = n01r; p01i = n01i;
            p10r = n10r; p10i = n10i; p11r = n11r; p11i = n11i;
        }

        __syncthreads();               // wait for vector warps' exch writes
        if (fq < nf) {
            float4 v  = exch[pair * 32 + lane];
            // (Ur,Ui,Vr,Vi) = P * v
            float Ur = p00r * v.x - p00i * v.y + p01r * v.z - p01i * v.w;
            float Ui = p00r * v.y + p00i * v.x + p01r * v.w + p01i * v.z;
            float Vr = p10r * v.x - p10i * v.y + p11r * v.z - p11i * v.w;
            float Vi = p10r * v.y + p10i * v.x + p11r * v.w + p11i * v.z;

            float Nr = Ur + Vr, Ni = Ui + Vi;
            float Dr = Ur - Vr, Di = Ui - Vi;

            float n2 = fmaxf(Nr * Nr + Ni * Ni, 1e-30f);
            float d2 = fmaxf(Dr * Dr + Di * Di, 1e-30f);
            float A  = Nr * Dr + Ni * Di;
            float B  = Ni * Dr - Nr * Di;

            float e1 = sc_lrho0 + log10f(n2) - log10f(d2) - log10f(orhoa[fq]);
            float ph = atan2f(A + B, A - B) * RAD2DEG_F;
            float e2 = ph - ophase[fq];
            lr = e1 * e1;
            lp = e2 * e2;
        }
    }
    if (role == 0) __syncthreads();    // vector warps join the same barrier

    // deterministic block reduction (256 threads = 8 warps; vector warps add 0)
    const unsigned FULL = 0xffffffffu;
    #pragma unroll
    for (int o = 16; o > 0; o >>= 1) {
        lr += __shfl_down_sync(FULL, lr, o);
        lp += __shfl_down_sync(FULL, lp, o);
    }
    if (lane == 0) red[wid] = make_float2(lr, lp);
    __syncthreads();
    if (tid == 0) {
        float slr = 0.0f, slp = 0.0f;
        #pragma unroll
        for (int w = 0; w < 8; ++w) { slr += red[w].x; slp += red[w].y; }
        g_part[blockIdx.x] = make_float2(slr, slp);
        __threadfence();
        unsigned t = atomicAdd(&g_ticket, 1u);
        is_last = (t == gridDim.x - 1) ? 1 : 0;
    }
    __syncthreads();

    if (is_last) {
        __threadfence();
        float flr = 0.0f, flp = 0.0f;
        if (tid < 32) {
            for (int i = tid; i < (int)gridDim.x; i += 32) {
                volatile float* vp = (volatile float*)&g_part[i];
                flr += vp[0];
                flp += vp[1];
            }
            #pragma unroll
            for (int o = 16; o > 0; o >>= 1) {
                flr += __shfl_down_sync(FULL, flr, o);
                flp += __shfl_down_sync(FULL, flp, o);
            }
            if (tid == 0) {
                float mlr = flr * inv_nf;
                float mlp = flp * inv_nf;
                out[0] = mlr + 10.0f * mlp;   // LAMBDA_RHOA=1, LAMBDA_PHASE=10
                out[1] = mlr;
                out[2] = mlp;
                g_ticket = 0;                 // reset for next graph replay
            }
        }
    }
}

extern "C" void kernel_launch(void* const* d_in, const int* in_sizes, int n_in,
                              void* d_out, int out_size)
{
    const float* res = (const float*)d_in[0];
    const float* th  = (const float*)d_in[1];
    const float* fr  = (const float*)d_in[2];
    const float* orh = (const float*)d_in[3];
    const float* oph = (const float*)d_in[4];
    int nz = in_sizes[0];
    int nf = in_sizes[2];

    const int threads = 256;               // 8 warps: 4 vector + 4 matrix
    int blocks = (nf + 127) / 128;         // 128 freqs per block -> 128 blocks
    if (blocks > 256) blocks = 256;

    mt_fused<<<blocks, threads>>>(res, th, fr, orh, oph,
                                  (float*)d_out, nz, nf, 1.0f / (float)nf);
}